// round 15
// baseline (speedup 1.0000x reference)
#include <cuda_runtime.h>
#include <cuda_bf16.h>
#include <cstdint>
#include <cstddef>

// Problem constants (fixed by the reference)
#define NROWS 8192
#define NCOLS 8192
#define NC4   (NCOLS/4)                // 2048 float4 per row
#define RB 32
#define CB 32
#define HID 100
#define DIO (RB*CB)
#define RSPLIT 16                      // row-phase split per row-block
#define NITEMS (RB*RSPLIT)             // 512 dynamic phase-1 items
#define NB_CTAS (148*2)                // 296: exactly 2 CTAs on every SM

// Scratch (no cudaMalloc allowed)
__device__ float4 g_rowsum4[RB * RSPLIT * NC4];  // 16 MB: per (rb,s) column sums
__device__ float  g_blk[DIO];
__device__ int    g_rowb[RB + 1];
__device__ int    g_colb[CB + 1];
__device__ int    g_work;
__device__ unsigned g_bar_arrive = 0;
__device__ volatile unsigned g_bar_gen = 0;

// Generation-based grid barrier: safe across graph replays (self-resetting),
// deadlock-free because all NB_CTAS are co-resident (2 CTAs/SM exactly).
__device__ __forceinline__ void grid_barrier() {
    __syncthreads();
    if (threadIdx.x == 0) {
        __threadfence();
        unsigned gen = g_bar_gen;
        unsigned a = atomicAdd(&g_bar_arrive, 1u);
        if (a == NB_CTAS - 1u) {
            atomicExch(&g_bar_arrive, 0u);
            __threadfence();
            g_bar_gen = gen + 1u;
        } else {
            while (g_bar_gen == gen) { }
            __threadfence();
        }
    }
    __syncthreads();
}

__global__ __launch_bounds__(256, 2)
void k_fused(const float* __restrict__ X,
             const int* __restrict__ row_ids,
             const int* __restrict__ col_ids,
             const float* __restrict__ W1, const float* __restrict__ b1,
             const float* __restrict__ W2, const float* __restrict__ b2,
             const float* __restrict__ W3, const float* __restrict__ b3,
             float* __restrict__ out) {
    __shared__ float xs[DIO];
    __shared__ float h1p[800];
    __shared__ float h2p[1000];
    __shared__ float h1[HID];
    __shared__ float h2[HID];

    const int t = threadIdx.x;
    const int warp = t >> 5, lane = t & 31;

    // ---------------- Phase A: boundaries via adjacent-diff (CTAs 0..31) ----
    if (blockIdx.x < 32) {
        const bool rowpass = (blockIdx.x < 16);
        const int  slice   = rowpass ? blockIdx.x : (blockIdx.x - 16);
        const int  nb  = rowpass ? RB : CB;
        const int  n   = rowpass ? NROWS : NCOLS;
        const int* ids = rowpass ? row_ids : col_ids;
        int*   bnd = rowpass ? g_rowb : g_colb;
        float* o   = out + DIO + (rowpass ? 0 : (RB + 1));
        const int i = slice * 512 + t * 2;
        #pragma unroll
        for (int d = 0; d < 2; d++) {
            int g = i + d;
            if (g < n) {
                int cur  = ids[g];
                int prev = (g == 0) ? -1 : ids[g - 1];
                for (int k = prev + 1; k <= cur; k++) { bnd[k] = g; o[k] = (float)g; }
                if (g == n - 1)
                    for (int k = cur + 1; k <= nb; k++) { bnd[k] = n; o[k] = (float)n; }
            }
        }
    } else if (blockIdx.x == 32 && t == 0) {
        g_work = 0;
    }

    grid_barrier();

    // ---------------- Phase 1: dynamic (rb,s) items, sequential full rows ---
    // Item (rb, s): rows rlo+s, rlo+s+16, ... Each row read as one contiguous
    // 32KB burst (thread t owns float4 cols t+256p, p=0..7). Double-buffered:
    // next row's 8 loads issue before current row's accumulate -> 16 LDG.128
    // in flight per thread. Sole-owner store into the (rb,s) scratch slice.
    {
        const float4* X4 = (const float4*)X;
        for (;;) {
            int item;
            if (t == 0) item = atomicAdd(&g_work, 1);
            item = __shfl_sync(0xFFFFFFFFu, item, 0);       // warp 0 value...
            __shared__ int s_item;
            if (t == 0) s_item = item;
            __syncthreads();
            item = s_item;
            if (item >= NITEMS) break;

            const int rb = item >> 4;
            const int s  = item & (RSPLIT - 1);
            const int rlo = g_rowb[rb], rhi = g_rowb[rb + 1];

            float4 acc[8];
            #pragma unroll
            for (int p = 0; p < 8; p++) acc[p] = make_float4(0.f, 0.f, 0.f, 0.f);

            int r = rlo + s;
            if (r < rhi) {
                float4 v[8];
                const float4* row = X4 + (size_t)r * NC4 + t;
                #pragma unroll
                for (int p = 0; p < 8; p++) v[p] = __ldcs(row + 256 * p);
                for (r += RSPLIT; r < rhi; r += RSPLIT) {
                    const float4* row2 = X4 + (size_t)r * NC4 + t;
                    float4 nv[8];
                    #pragma unroll
                    for (int p = 0; p < 8; p++) nv[p] = __ldcs(row2 + 256 * p);
                    #pragma unroll
                    for (int p = 0; p < 8; p++) {
                        acc[p].x += v[p].x; acc[p].y += v[p].y;
                        acc[p].z += v[p].z; acc[p].w += v[p].w;
                        v[p] = nv[p];
                    }
                }
                #pragma unroll
                for (int p = 0; p < 8; p++) {
                    acc[p].x += v[p].x; acc[p].y += v[p].y;
                    acc[p].z += v[p].z; acc[p].w += v[p].w;
                }
            }

            float4* dst = g_rowsum4 + ((size_t)(rb * RSPLIT + s)) * NC4 + t;
            #pragma unroll
            for (int p = 0; p < 8; p++) dst[256 * p] = acc[p];
            __syncthreads();   // all threads done before next s_item broadcast
        }
    }

    grid_barrier();

    // ---------------- Phase 2: column-block reduce (CTAs 0..127) -----------
    // One warp per (rb, cb): rb = bid>>2, cb = (bid&3)*8 + warp.
    // Sums the 16 s-slices over the column range [clo, chi).
    if (blockIdx.x < 128) {
        const int rb = blockIdx.x >> 2;
        const int cb = (blockIdx.x & 3) * 8 + warp;
        const int clo = g_colb[cb], chi = g_colb[cb + 1];
        const float* base = (const float*)(g_rowsum4 + (size_t)rb * RSPLIT * NC4);

        float a = 0.f;
        for (int j = clo + lane; j < chi; j += 32) {
            float p0 = 0.f, p1 = 0.f, p2 = 0.f, p3 = 0.f;
            #pragma unroll
            for (int s = 0; s < RSPLIT; s += 4) {            // 4-deep batches
                p0 += base[(s    ) * NCOLS + j];
                p1 += base[(s + 1) * NCOLS + j];
                p2 += base[(s + 2) * NCOLS + j];
                p3 += base[(s + 3) * NCOLS + j];
            }
            a += (p0 + p1) + (p2 + p3);
        }
        #pragma unroll
        for (int o = 16; o; o >>= 1) a += __shfl_xor_sync(0xFFFFFFFFu, a, o);
        if (lane == 0) g_blk[rb * CB + cb] = a;              // sole owner
    }

    grid_barrier();

    // ---------------- Phase 3: MLP + sigmoid (CTA 0, 256 threads) ----------
    if (blockIdx.x != 0) return;

    #pragma unroll
    for (int d = 0; d < 4; d++) {
        int b = t + d * 256;
        int rb = b >> 5, cbi = b & 31;
        float rc = (float)(g_rowb[rb + 1] - g_rowb[rb]);
        float cc = (float)(g_colb[cbi + 1] - g_colb[cbi]);
        xs[b] = g_blk[b] / fmaxf(rc * cc, 1.0f);
    }
    __syncthreads();

    // layer 1: h1 = relu(x @ W1 + b1); 8 K-slices x 100 outputs
    for (int u = t; u < 800; u += 256) {
        const int j  = u % HID;
        const int i0 = (u / HID) * 128;
        float acc = 0.f;
        #pragma unroll 16
        for (int i = 0; i < 128; i++)
            acc += xs[i0 + i] * W1[(size_t)(i0 + i) * HID + j];
        h1p[u] = acc;
    }
    __syncthreads();
    if (t < HID) {
        float a = b1[t];
        #pragma unroll
        for (int sl = 0; sl < 8; sl++) a += h1p[sl * HID + t];
        h1[t] = fmaxf(a, 0.f);
    }
    __syncthreads();

    // layer 2: h2 = relu(h1 @ W2 + b2); 10 K-slices x 100
    for (int u = t; u < 1000; u += 256) {
        const int j  = u % HID;
        const int i0 = (u / HID) * 10;
        float acc = 0.f;
        #pragma unroll
        for (int i = 0; i < 10; i++)
            acc += h1[i0 + i] * W2[(i0 + i) * HID + j];
        h2p[u] = acc;
    }
    __syncthreads();
    if (t < HID) {
        float a = b2[t];
        #pragma unroll
        for (int sl = 0; sl < 10; sl++) a += h2p[sl * HID + t];
        h2[t] = fmaxf(a, 0.f);
    }
    __syncthreads();

    // layer 3: out = sigmoid(h2 @ W3 + b3), W3[100,1024]
    #pragma unroll
    for (int d = 0; d < 4; d++) {
        int j = t + d * 256;
        float a = b3[j];
        #pragma unroll 10
        for (int i = 0; i < HID; i++) a += h2[i] * W3[(size_t)i * DIO + j];
        out[j] = 1.0f / (1.0f + __expf(-a));
    }
}

extern "C" void kernel_launch(void* const* d_in, const int* in_sizes, int n_in,
                              void* d_out, int out_size) {
    const float* X       = (const float*)d_in[0];
    const int*   row_ids = (const int*)  d_in[1];
    const int*   col_ids = (const int*)  d_in[2];
    const float* W1      = (const float*)d_in[3];
    const float* b1      = (const float*)d_in[4];
    const float* W2      = (const float*)d_in[5];
    const float* b2      = (const float*)d_in[6];
    const float* W3      = (const float*)d_in[7];
    const float* b3      = (const float*)d_in[8];
    float* out = (float*)d_out;

    k_fused<<<NB_CTAS, 256>>>(X, row_ids, col_ids, W1, b1, W2, b2, W3, b3, out);
}

// round 16
// speedup vs baseline: 1.0755x; 1.0755x over previous
#include <cuda_runtime.h>
#include <cuda_bf16.h>
#include <cstdint>
#include <cstddef>

// Problem constants (fixed by the reference)
#define NROWS 8192
#define NCOLS 8192
#define NC4   (NCOLS/4)                // 2048 float4 per row
#define RB 32
#define CB 32
#define HID 100
#define DIO (RB*CB)
#define RSPLIT 8                       // row-phase split per row-block
#define NB_CTAS 256                    // grid; all co-resident (2 CTAs/SM cap = 296)

// Scratch (no cudaMalloc allowed)
__device__ float4 g_rowsum4[RB * RSPLIT * NC4];  // 8 MB: per (rb, s) column sums
__device__ float  g_blk[DIO];
__device__ int    g_rowb[RB + 1];
__device__ int    g_colb[CB + 1];
__device__ unsigned g_bar_arrive = 0;
__device__ volatile unsigned g_bar_gen = 0;

// Generation-based grid barrier: safe across graph replays (self-resetting),
// deadlock-free because all NB_CTAS are co-resident (<=2 CTAs/SM).
__device__ __forceinline__ void grid_barrier() {
    __syncthreads();
    if (threadIdx.x == 0) {
        __threadfence();
        unsigned gen = g_bar_gen;
        unsigned a = atomicAdd(&g_bar_arrive, 1u);
        if (a == NB_CTAS - 1u) {
            atomicExch(&g_bar_arrive, 0u);
            __threadfence();
            g_bar_gen = gen + 1u;
        } else {
            while (g_bar_gen == gen) { }
            __threadfence();
        }
    }
    __syncthreads();
}

__global__ __launch_bounds__(256, 2)
void k_fused(const float* __restrict__ X,
             const int* __restrict__ row_ids,
             const int* __restrict__ col_ids,
             const float* __restrict__ W1, const float* __restrict__ b1,
             const float* __restrict__ W2, const float* __restrict__ b2,
             const float* __restrict__ W3, const float* __restrict__ b3,
             float* __restrict__ out) {
    __shared__ float xs[DIO];
    __shared__ float h1p[800];
    __shared__ float h2p[1000];
    __shared__ float h1[HID];
    __shared__ float h2[HID];

    const int t = threadIdx.x;
    const int warp = t >> 5, lane = t & 31;

    // ---------------- Phase A: boundaries via adjacent-diff (CTAs 0..31) ----
    if (blockIdx.x < 32) {
        const bool rowpass = (blockIdx.x < 16);
        const int  slice   = rowpass ? blockIdx.x : (blockIdx.x - 16);
        const int  nb  = rowpass ? RB : CB;
        const int  n   = rowpass ? NROWS : NCOLS;
        const int* ids = rowpass ? row_ids : col_ids;
        int*   bnd = rowpass ? g_rowb : g_colb;
        float* o   = out + DIO + (rowpass ? 0 : (RB + 1));
        const int i = slice * 512 + t * 2;
        #pragma unroll
        for (int d = 0; d < 2; d++) {
            int g = i + d;
            if (g < n) {
                int cur  = ids[g];
                int prev = (g == 0) ? -1 : ids[g - 1];
                for (int k = prev + 1; k <= cur; k++) { bnd[k] = g; o[k] = (float)g; }
                if (g == n - 1)
                    for (int k = cur + 1; k <= nb; k++) { bnd[k] = n; o[k] = (float)n; }
            }
        }
    }

    grid_barrier();

    // ---------------- Phase 1: sequential full-row partial sums ------------
    // CTA (rb = bid>>3, s = bid&7): rows rlo+s, rlo+s+8, ... Two rows per
    // iteration: 16 independent LDG.128.CS issue before any FADD (no copies,
    // no extra scratch) -> ~32KB in flight per SM. Thread t owns float4
    // columns t+256p, p=0..7. Sole-owner store into the (rb,s) slice.
    {
        const int rb = blockIdx.x >> 3;
        const int s  = blockIdx.x & 7;
        const int rlo = g_rowb[rb], rhi = g_rowb[rb + 1];
        const float4* X4 = (const float4*)X;

        float4 acc[8];
        #pragma unroll
        for (int p = 0; p < 8; p++) acc[p] = make_float4(0.f, 0.f, 0.f, 0.f);

        int r = rlo + s;
        for (; r + RSPLIT < rhi; r += 2 * RSPLIT) {
            const float4* ra = X4 + (size_t)r * NC4 + t;
            const float4* rb2 = X4 + (size_t)(r + RSPLIT) * NC4 + t;
            float4 va[8], vb[8];
            #pragma unroll
            for (int p = 0; p < 8; p++) va[p] = __ldcs(ra + 256 * p);
            #pragma unroll
            for (int p = 0; p < 8; p++) vb[p] = __ldcs(rb2 + 256 * p);
            #pragma unroll
            for (int p = 0; p < 8; p++) {
                acc[p].x += va[p].x + vb[p].x;
                acc[p].y += va[p].y + vb[p].y;
                acc[p].z += va[p].z + vb[p].z;
                acc[p].w += va[p].w + vb[p].w;
            }
        }
        if (r < rhi) {                                  // tail single row
            const float4* ra = X4 + (size_t)r * NC4 + t;
            #pragma unroll
            for (int p = 0; p < 8; p++) {
                float4 v = __ldcs(ra + 256 * p);
                acc[p].x += v.x; acc[p].y += v.y;
                acc[p].z += v.z; acc[p].w += v.w;
            }
        }

        float4* dst = g_rowsum4 + ((size_t)(rb * RSPLIT + s)) * NC4 + t;
        #pragma unroll
        for (int p = 0; p < 8; p++) dst[256 * p] = acc[p];
    }

    grid_barrier();

    // ---------------- Phase 2: column-block reduce (CTAs 0..127) -----------
    // One warp per (rb, cb): rb = bid>>2, cb = (bid&3)*8 + warp.
    // Sums the 8 s-slices over the column range [clo, chi).
    if (blockIdx.x < 128) {
        const int rb = blockIdx.x >> 2;
        const int cb = (blockIdx.x & 3) * 8 + warp;
        const int clo = g_colb[cb], chi = g_colb[cb + 1];
        const float* base = (const float*)(g_rowsum4 + (size_t)rb * RSPLIT * NC4);

        float a = 0.f;
        for (int j = clo + lane; j < chi; j += 32) {
            float p0 = 0.f, p1 = 0.f, p2 = 0.f, p3 = 0.f;
            #pragma unroll
            for (int s = 0; s < RSPLIT; s += 4) {        // 8 loads in flight
                p0 += base[(s    ) * NCOLS + j];
                p1 += base[(s + 1) * NCOLS + j];
                p2 += base[(s + 2) * NCOLS + j];
                p3 += base[(s + 3) * NCOLS + j];
            }
            a += (p0 + p1) + (p2 + p3);
        }
        #pragma unroll
        for (int o = 16; o; o >>= 1) a += __shfl_xor_sync(0xFFFFFFFFu, a, o);
        if (lane == 0) g_blk[rb * CB + cb] = a;          // sole owner
    }

    grid_barrier();

    // ---------------- Phase 3: MLP + sigmoid (CTA 0, 256 threads) ----------
    if (blockIdx.x != 0) return;

    #pragma unroll
    for (int d = 0; d < 4; d++) {
        int b = t + d * 256;
        int rb = b >> 5, cbi = b & 31;
        float rc = (float)(g_rowb[rb + 1] - g_rowb[rb]);
        float cc = (float)(g_colb[cbi + 1] - g_colb[cbi]);
        xs[b] = g_blk[b] / fmaxf(rc * cc, 1.0f);
    }
    __syncthreads();

    // layer 1: h1 = relu(x @ W1 + b1); 8 K-slices x 100 outputs
    for (int u = t; u < 800; u += 256) {
        const int j  = u % HID;
        const int i0 = (u / HID) * 128;
        float acc = 0.f;
        #pragma unroll 16
        for (int i = 0; i < 128; i++)
            acc += xs[i0 + i] * W1[(size_t)(i0 + i) * HID + j];
        h1p[u] = acc;
    }
    __syncthreads();
    if (t < HID) {
        float a = b1[t];
        #pragma unroll
        for (int sl = 0; sl < 8; sl++) a += h1p[sl * HID + t];
        h1[t] = fmaxf(a, 0.f);
    }
    __syncthreads();

    // layer 2: h2 = relu(h1 @ W2 + b2); 10 K-slices x 100
    for (int u = t; u < 1000; u += 256) {
        const int j  = u % HID;
        const int i0 = (u / HID) * 10;
        float acc = 0.f;
        #pragma unroll
        for (int i = 0; i < 10; i++)
            acc += h1[i0 + i] * W2[(i0 + i) * HID + j];
        h2p[u] = acc;
    }
    __syncthreads();
    if (t < HID) {
        float a = b2[t];
        #pragma unroll
        for (int sl = 0; sl < 10; sl++) a += h2p[sl * HID + t];
        h2[t] = fmaxf(a, 0.f);
    }
    __syncthreads();

    // layer 3: out = sigmoid(h2 @ W3 + b3), W3[100,1024]
    #pragma unroll
    for (int d = 0; d < 4; d++) {
        int j = t + d * 256;
        float a = b3[j];
        #pragma unroll 10
        for (int i = 0; i < HID; i++) a += h2[i] * W3[(size_t)i * DIO + j];
        out[j] = 1.0f / (1.0f + __expf(-a));
    }
}

extern "C" void kernel_launch(void* const* d_in, const int* in_sizes, int n_in,
                              void* d_out, int out_size) {
    const float* X       = (const float*)d_in[0];
    const int*   row_ids = (const int*)  d_in[1];
    const int*   col_ids = (const int*)  d_in[2];
    const float* W1      = (const float*)d_in[3];
    const float* b1      = (const float*)d_in[4];
    const float* W2      = (const float*)d_in[5];
    const float* b2      = (const float*)d_in[6];
    const float* W3      = (const float*)d_in[7];
    const float* b3      = (const float*)d_in[8];
    float* out = (float*)d_out;

    k_fused<<<NB_CTAS, 256>>>(X, row_ids, col_ids, W1, b1, W2, b2, W3, b3, out);
}